// round 1
// baseline (speedup 1.0000x reference)
#include <cuda_runtime.h>

#define NBATCH 2
#define PPB (128*128*128)       // points per batch
#define NB 64                   // number of bins
#define R 2                     // window radius (5-wide window; truncation error ~2e-6)
#define W 5
#define BLOCKS_PER_BATCH 296
#define THREADS 256

// Scratch: per-batch joint histogram (no device allocs allowed)
__device__ float g_hist[NBATCH][NB * NB];

__global__ void zero_kernel() {
    int i = blockIdx.x * blockDim.x + threadIdx.x;
    if (i < NBATCH * NB * NB) ((float*)g_hist)[i] = 0.0f;
}

__global__ __launch_bounds__(THREADS) void hist_kernel(const float* __restrict__ x,
                                                       const float* __restrict__ y) {
    __shared__ float sh[NB * NB];
    const int n = blockIdx.y;
    for (int i = threadIdx.x; i < NB * NB; i += blockDim.x) sh[i] = 0.0f;
    __syncthreads();

    // Constants (compile-time folded)
    const float DELTA = 1.0f / 63.0f;                       // bin spacing (linspace(0,1,64))
    const double SIGd = 0.015625 / 2.3548200450309493;      // FWHM-derived sigma
    const float C  = (float)(1.0 / (2.0 * SIGd * SIGd));    // 1/(2 sigma^2)
    const float GN = (float)(1.0 / (2.5066282746310002 * SIGd)); // gaussian norm
    const float q = __expf(-C * DELTA * DELTA);
    const float s = q * q;
    const float twoCD = 2.0f * C * DELTA;

    const float4* x4 = (const float4*)(x + (size_t)n * PPB);
    const float4* y4 = (const float4*)(y + (size_t)n * PPB);
    const int nvec = PPB / 4;
    const int stride = gridDim.x * blockDim.x;

    for (int v = blockIdx.x * blockDim.x + threadIdx.x; v < nvec; v += stride) {
        float4 xv = x4[v];
        float4 yv = y4[v];
        float xs[4] = {xv.x, xv.y, xv.z, xv.w};
        float ys[4] = {yv.x, yv.y, yv.z, yv.w};
        #pragma unroll
        for (int e = 0; e < 4; e++) {
            // ---- x weights: w_k = GN * exp(-C*(a - k*DELTA)^2), k = -R..R
            // via geometric recurrence: ratio_k = t*q*s^k (up), ti*q*s^k (down)
            float fx = xs[e] * 63.0f;
            int ix = __float2int_rn(fx);
            float ax = (fx - (float)ix) * DELTA;     // offset from nearest bin center
            float wx[W];
            {
                float w0 = GN * __expf(-C * ax * ax);
                float t  = __expf(twoCD * ax);
                float ti = __frcp_rn(t);
                wx[R] = w0;
                float r = t * q;  wx[R + 1] = wx[R] * r;      r *= s; wx[R + 2] = wx[R + 1] * r;
                float r2 = ti * q; wx[R - 1] = wx[R] * r2;    r2 *= s; wx[R - 2] = wx[R - 1] * r2;
            }
            // ---- y weights
            float fy = ys[e] * 63.0f;
            int iy = __float2int_rn(fy);
            float ay = (fy - (float)iy) * DELTA;
            float wy[W];
            {
                float w0 = GN * __expf(-C * ay * ay);
                float t  = __expf(twoCD * ay);
                float ti = __frcp_rn(t);
                wy[R] = w0;
                float r = t * q;  wy[R + 1] = wy[R] * r;      r *= s; wy[R + 2] = wy[R + 1] * r;
                float r2 = ti * q; wy[R - 1] = wy[R] * r2;    r2 *= s; wy[R - 2] = wy[R - 1] * r2;
            }
            // ---- edge handling: zero weight + clamp index (adds of 0 are harmless)
            int row[W], col[W];
            #pragma unroll
            for (int k = 0; k < W; k++) {
                int bx = ix - R + k;
                if ((unsigned)bx >= (unsigned)NB) { wx[k] = 0.0f; bx = bx < 0 ? 0 : NB - 1; }
                row[k] = bx * NB;
                int by = iy - R + k;
                if ((unsigned)by >= (unsigned)NB) { wy[k] = 0.0f; by = by < 0 ? 0 : NB - 1; }
                col[k] = by;
            }
            // ---- 5x5 outer-product scatter into shared histogram
            #pragma unroll
            for (int i = 0; i < W; i++) {
                float wxi = wx[i];
                int ro = row[i];
                #pragma unroll
                for (int j = 0; j < W; j++) {
                    atomicAdd(&sh[ro + col[j]], wxi * wy[j]);
                }
            }
        }
    }

    __syncthreads();
    for (int i = threadIdx.x; i < NB * NB; i += blockDim.x) {
        float v = sh[i];
        if (v != 0.0f) atomicAdd(&g_hist[n][i], v);
    }
}

__global__ __launch_bounds__(256) void finalize_kernel(float* __restrict__ out) {
    __shared__ float red[256];
    __shared__ float px[NB], py[NB];
    const float EPS = 1e-5f;
    float result = 0.0f;

    for (int n = 0; n < NBATCH; n++) {
        const float* h = g_hist[n];
        // total mass
        float t = 0.0f;
        for (int i = threadIdx.x; i < NB * NB; i += 256) t += h[i];
        red[threadIdx.x] = t; __syncthreads();
        for (int ofs = 128; ofs > 0; ofs >>= 1) {
            if (threadIdx.x < ofs) red[threadIdx.x] += red[threadIdx.x + ofs];
            __syncthreads();
        }
        float inv = 1.0f / (red[0] + EPS);
        __syncthreads();

        // marginals
        if (threadIdx.x < NB) {
            float sx = 0.0f, sy = 0.0f;
            for (int c = 0; c < NB; c++) {
                sx += h[threadIdx.x * NB + c];
                sy += h[c * NB + threadIdx.x];
            }
            px[threadIdx.x] = sx * inv;
            py[threadIdx.x] = sy * inv;
        }
        __syncthreads();

        // joint entropy
        float ej = 0.0f;
        for (int i = threadIdx.x; i < NB * NB; i += 256) {
            float p = h[i] * inv;
            ej += p * __logf(p + EPS);
        }
        red[threadIdx.x] = ej; __syncthreads();
        for (int ofs = 128; ofs > 0; ofs >>= 1) {
            if (threadIdx.x < ofs) red[threadIdx.x] += red[threadIdx.x + ofs];
            __syncthreads();
        }
        float ent_joint = -red[0];
        __syncthreads();

        // marginal entropies (ent_x + ent_y together)
        float exy = 0.0f;
        if (threadIdx.x < NB) {
            exy = px[threadIdx.x] * __logf(px[threadIdx.x] + EPS)
                + py[threadIdx.x] * __logf(py[threadIdx.x] + EPS);
        }
        red[threadIdx.x] = exy; __syncthreads();
        for (int ofs = 128; ofs > 0; ofs >>= 1) {
            if (threadIdx.x < ofs) red[threadIdx.x] += red[threadIdx.x + ofs];
            __syncthreads();
        }
        float ent_xy = -red[0];
        __syncthreads();

        result += ent_xy / ent_joint;
    }

    if (threadIdx.x == 0) out[0] = -result * (1.0f / NBATCH);
}

extern "C" void kernel_launch(void* const* d_in, const int* in_sizes, int n_in,
                              void* d_out, int out_size) {
    const float* x = (const float*)d_in[0];
    const float* y = (const float*)d_in[1];
    float* out = (float*)d_out;

    zero_kernel<<<(NBATCH * NB * NB + 255) / 256, 256>>>();
    hist_kernel<<<dim3(BLOCKS_PER_BATCH, NBATCH), THREADS>>>(x, y);
    finalize_kernel<<<1, 256>>>(out);
}

// round 3
// speedup vs baseline: 2.2276x; 2.2276x over previous
#include <cuda_runtime.h>

#define NBATCH 2
#define PPB (128*128*128)       // points per batch
#define NB 64                   // number of bins
#define BLOCKS_PER_BATCH 296
#define THREADS 256

// Scratch: per-batch joint histogram. Zero-initialized at module load;
// finalize_kernel re-zeroes it after use so every graph replay starts clean.
__device__ float g_hist[NBATCH][NB * NB];

__global__ __launch_bounds__(THREADS) void hist_kernel(const float* __restrict__ x,
                                                       const float* __restrict__ y) {
    __shared__ float sh[NB * NB];
    const int n = blockIdx.y;
    for (int i = threadIdx.x; i < NB * NB; i += blockDim.x) sh[i] = 0.0f;
    __syncthreads();

    // K2 = C * DELTA^2 where C = 1/(2 sigma^2), DELTA = 1/63, sigma = (1/64)/2.3548...
    // All constant scale factors (GN etc.) cancel under normalization and are dropped.
    const float K2 = (float)( (1.0/63.0)*(1.0/63.0)
                     / (2.0 * (0.015625/2.3548200450309493) * (0.015625/2.3548200450309493)) );

    const float4* x4 = (const float4*)(x + (size_t)n * PPB);
    const float4* y4 = (const float4*)(y + (size_t)n * PPB);
    const int nvec = PPB / 4;
    const int stride = gridDim.x * blockDim.x;

    for (int v = blockIdx.x * blockDim.x + threadIdx.x; v < nvec; v += stride) {
        float4 xv = x4[v];
        float4 yv = y4[v];
        float xs[4] = {xv.x, xv.y, xv.z, xv.w};
        float ys[4] = {yv.x, yv.y, yv.z, yv.w};
        #pragma unroll
        for (int e = 0; e < 4; e++) {
            // x weights: u in [-0.5, 0.5] is offset (in bin units) from nearest bin center
            float fx = xs[e] * 63.0f;
            int ix = __float2int_rn(fx);
            float ux = fx - (float)ix;
            float wxm = __expf(-K2 * (ux + 1.0f) * (ux + 1.0f));
            float wx0 = __expf(-K2 * ux * ux);
            float wxp = __expf(-K2 * (ux - 1.0f) * (ux - 1.0f));
            // y weights
            float fy = ys[e] * 63.0f;
            int iy = __float2int_rn(fy);
            float uy = fy - (float)iy;
            float wym = __expf(-K2 * (uy + 1.0f) * (uy + 1.0f));
            float wy0 = __expf(-K2 * uy * uy);
            float wyp = __expf(-K2 * (uy - 1.0f) * (uy - 1.0f));

            // edge handling: zero weight + clamp index (adds of 0 are harmless)
            int rm = ix - 1, r0 = ix, rp = ix + 1;
            if (rm < 0)      { wxm = 0.0f; rm = 0; }
            if (rp > NB - 1) { wxp = 0.0f; rp = NB - 1; }
            int cm = iy - 1, c0 = iy, cp = iy + 1;
            if (cm < 0)      { wym = 0.0f; cm = 0; }
            if (cp > NB - 1) { wyp = 0.0f; cp = NB - 1; }
            rm *= NB; r0 *= NB; rp *= NB;

            // 3x3 outer-product scatter
            atomicAdd(&sh[rm + cm], wxm * wym);
            atomicAdd(&sh[rm + c0], wxm * wy0);
            atomicAdd(&sh[rm + cp], wxm * wyp);
            atomicAdd(&sh[r0 + cm], wx0 * wym);
            atomicAdd(&sh[r0 + c0], wx0 * wy0);
            atomicAdd(&sh[r0 + cp], wx0 * wyp);
            atomicAdd(&sh[rp + cm], wxp * wym);
            atomicAdd(&sh[rp + c0], wxp * wy0);
            atomicAdd(&sh[rp + cp], wxp * wyp);
        }
    }

    __syncthreads();
    for (int i = threadIdx.x; i < NB * NB; i += blockDim.x) {
        float v = sh[i];
        if (v != 0.0f) atomicAdd(&g_hist[n][i], v);
    }
}

__global__ __launch_bounds__(256) void finalize_kernel(float* __restrict__ out) {
    __shared__ float red[256];
    __shared__ float px[NB], py[NB];
    const float EPS = 1e-5f;
    float result = 0.0f;

    for (int n = 0; n < NBATCH; n++) {
        const float* h = g_hist[n];
        // total mass
        float t = 0.0f;
        for (int i = threadIdx.x; i < NB * NB; i += 256) t += h[i];
        red[threadIdx.x] = t; __syncthreads();
        for (int ofs = 128; ofs > 0; ofs >>= 1) {
            if (threadIdx.x < ofs) red[threadIdx.x] += red[threadIdx.x + ofs];
            __syncthreads();
        }
        float inv = 1.0f / (red[0] + EPS);
        __syncthreads();

        // marginals
        if (threadIdx.x < NB) {
            float sx = 0.0f, sy = 0.0f;
            for (int c = 0; c < NB; c++) {
                sx += h[threadIdx.x * NB + c];
                sy += h[c * NB + threadIdx.x];
            }
            px[threadIdx.x] = sx * inv;
            py[threadIdx.x] = sy * inv;
        }
        __syncthreads();

        // joint entropy
        float ej = 0.0f;
        for (int i = threadIdx.x; i < NB * NB; i += 256) {
            float p = h[i] * inv;
            ej += p * __logf(p + EPS);
        }
        red[threadIdx.x] = ej; __syncthreads();
        for (int ofs = 128; ofs > 0; ofs >>= 1) {
            if (threadIdx.x < ofs) red[threadIdx.x] += red[threadIdx.x + ofs];
            __syncthreads();
        }
        float ent_joint = -red[0];
        __syncthreads();

        // marginal entropies (ent_x + ent_y together)
        float exy = 0.0f;
        if (threadIdx.x < NB) {
            exy = px[threadIdx.x] * __logf(px[threadIdx.x] + EPS)
                + py[threadIdx.x] * __logf(py[threadIdx.x] + EPS);
        }
        red[threadIdx.x] = exy; __syncthreads();
        for (int ofs = 128; ofs > 0; ofs >>= 1) {
            if (threadIdx.x < ofs) red[threadIdx.x] += red[threadIdx.x + ofs];
            __syncthreads();
        }
        float ent_xy = -red[0];
        __syncthreads();

        result += ent_xy / ent_joint;
    }

    if (threadIdx.x == 0) out[0] = -result * (1.0f / NBATCH);

    // Re-zero scratch so the next graph replay starts from a clean histogram.
    for (int i = threadIdx.x; i < NBATCH * NB * NB; i += 256)
        ((float*)g_hist)[i] = 0.0f;
}

extern "C" void kernel_launch(void* const* d_in, const int* in_sizes, int n_in,
                              void* d_out, int out_size) {
    const float* x = (const float*)d_in[0];
    const float* y = (const float*)d_in[1];
    float* out = (float*)d_out;

    hist_kernel<<<dim3(BLOCKS_PER_BATCH, NBATCH), THREADS>>>(x, y);
    finalize_kernel<<<1, 256>>>(out);
}

// round 4
// speedup vs baseline: 2.6413x; 1.1857x over previous
#include <cuda_runtime.h>
#include <cuda_fp16.h>

#define NBATCH 2
#define PPB (128*128*128)       // points per batch
#define NB 64                   // number of bins
#define NP 32                   // half2 pairs per row
#define BLOCKS_PER_BATCH 296
#define THREADS 256

// Scratch: per-batch joint histogram (float, for finalize precision).
// Zero at module load; finalize_kernel re-zeroes after use for graph replays.
__device__ float g_hist[NBATCH][NB * NB];

__global__ __launch_bounds__(THREADS) void hist_kernel(const float* __restrict__ x,
                                                       const float* __restrict__ y) {
    __shared__ __half2 sh2[NB * NP];   // 64 rows x 32 half2 pairs (=64 cols)
    const int n = blockIdx.y;
    for (int i = threadIdx.x; i < NB * NP; i += blockDim.x)
        ((unsigned int*)sh2)[i] = 0u;
    __syncthreads();

    // K2 = DELTA^2 / (2 sigma^2); DELTA = 1/63, sigma = (1/64)/(2*sqrt(2 ln 2)).
    // Constant scale factors cancel under p_joint normalization and are dropped.
    const float K2 = (float)( (1.0/63.0)*(1.0/63.0)
                     / (2.0 * (0.015625/2.3548200450309493) * (0.015625/2.3548200450309493)) );

    const float4* x4 = (const float4*)(x + (size_t)n * PPB);
    const float4* y4 = (const float4*)(y + (size_t)n * PPB);
    const int nvec = PPB / 4;
    const int stride = gridDim.x * blockDim.x;

    for (int v = blockIdx.x * blockDim.x + threadIdx.x; v < nvec; v += stride) {
        float4 xv = x4[v];
        float4 yv = y4[v];
        float xs[4] = {xv.x, xv.y, xv.z, xv.w};
        float ys[4] = {yv.x, yv.y, yv.z, yv.w};
        #pragma unroll
        for (int e = 0; e < 4; e++) {
            // x weights (row dim)
            float fx = xs[e] * 63.0f;
            int ix = __float2int_rn(fx);
            float ux = fx - (float)ix;
            float wxm = __expf(-K2 * (ux + 1.0f) * (ux + 1.0f));
            float wx0 = __expf(-K2 * ux * ux);
            float wxp = __expf(-K2 * (ux - 1.0f) * (ux - 1.0f));
            // y weights (col dim)
            float fy = ys[e] * 63.0f;
            int iy = __float2int_rn(fy);
            float uy = fy - (float)iy;
            float wym = __expf(-K2 * (uy + 1.0f) * (uy + 1.0f));
            float wy0 = __expf(-K2 * uy * uy);
            float wyp = __expf(-K2 * (uy - 1.0f) * (uy - 1.0f));

            // edges: zero weight + clamp index (zero adds harmless)
            int rm = ix - 1, r0 = ix, rp = ix + 1;
            if (rm < 0)      { wxm = 0.0f; rm = 0; }
            if (rp > NB - 1) { wxp = 0.0f; rp = NB - 1; }
            if (iy < 1)       wym = 0.0f;
            if (iy > NB - 2)  wyp = 0.0f;

            // pack 3 col taps {iy-1, iy, iy+1} into two aligned half2 pairs
            int par = iy & 1;
            int p0 = (iy - 1) >> 1;          // iy=0 -> -1 (clamped; its value is (0,0))
            int p1 = p0 + 1;                 // iy=63 -> 32 (clamped; its value is (0,0))
            if (p0 < 0)      p0 = 0;
            if (p1 > NP - 1) p1 = NP - 1;
            // par==1 (odd):  v0=(wym,wy0), v1=(wyp,0)
            // par==0 (even): v0=(0,wym),   v1=(wy0,wyp)
            float a0 = par ? wym : 0.0f;
            float b0 = par ? wy0 : wym;
            float a1 = par ? wyp : wy0;
            float b1 = par ? 0.0f : wyp;

            rm *= NP; r0 *= NP; rp *= NP;
            // 3 rows x 2 half2 atomics = 6 shared atomics per point
            atomicAdd(&sh2[rm + p0], __floats2half2_rn(a0 * wxm, b0 * wxm));
            atomicAdd(&sh2[rm + p1], __floats2half2_rn(a1 * wxm, b1 * wxm));
            atomicAdd(&sh2[r0 + p0], __floats2half2_rn(a0 * wx0, b0 * wx0));
            atomicAdd(&sh2[r0 + p1], __floats2half2_rn(a1 * wx0, b1 * wx0));
            atomicAdd(&sh2[rp + p0], __floats2half2_rn(a0 * wxp, b0 * wxp));
            atomicAdd(&sh2[rp + p1], __floats2half2_rn(a1 * wxp, b1 * wxp));
        }
    }

    __syncthreads();
    for (int i = threadIdx.x; i < NB * NP; i += blockDim.x) {
        float2 f = __half22float2(sh2[i]);
        if (f.x != 0.0f) atomicAdd(&g_hist[n][2 * i],     f.x);
        if (f.y != 0.0f) atomicAdd(&g_hist[n][2 * i + 1], f.y);
    }
}

__global__ __launch_bounds__(1024) void finalize_kernel(float* __restrict__ out) {
    __shared__ float warp_red[NBATCH][16];
    __shared__ float px[NBATCH][NB], py[NBATCH][NB];
    __shared__ float res[NBATCH];
    const float EPS = 1e-5f;
    const int tid = threadIdx.x;
    const int half = tid >> 9;           // which batch this half-block handles
    const int t = tid & 511;
    const int wih = t >> 5;              // warp index within half (0..15)
    const int lane = t & 31;
    const float* h = g_hist[half];

    // ---- total mass ----
    float s = 0.0f;
    for (int i = t; i < NB * NB; i += 512) s += h[i];
    #pragma unroll
    for (int o = 16; o; o >>= 1) s += __shfl_down_sync(0xffffffffu, s, o);
    if (lane == 0) warp_red[half][wih] = s;
    __syncthreads();
    if (wih == 0) {
        float v = (lane < 16) ? warp_red[half][lane] : 0.0f;
        #pragma unroll
        for (int o = 8; o; o >>= 1) v += __shfl_down_sync(0xffffffffu, v, o);
        if (lane == 0) warp_red[half][0] = 1.0f / (v + EPS);
    }
    __syncthreads();
    const float inv = warp_red[half][0];
    __syncthreads();

    // ---- marginals: 8 threads per row/col ----
    {
        int r = t >> 3, k = t & 7;
        float sx = 0.0f, sy = 0.0f;
        #pragma unroll
        for (int j = 0; j < 8; j++) {
            sx += h[r * NB + k * 8 + j];
            sy += h[(k * 8 + j) * NB + r];
        }
        sx += __shfl_down_sync(0xffffffffu, sx, 4, 8);
        sx += __shfl_down_sync(0xffffffffu, sx, 2, 8);
        sx += __shfl_down_sync(0xffffffffu, sx, 1, 8);
        sy += __shfl_down_sync(0xffffffffu, sy, 4, 8);
        sy += __shfl_down_sync(0xffffffffu, sy, 2, 8);
        sy += __shfl_down_sync(0xffffffffu, sy, 1, 8);
        if (k == 0) { px[half][r] = sx * inv; py[half][r] = sy * inv; }
    }
    __syncthreads();

    // ---- joint sum p*log(p+eps) ----
    float ej = 0.0f;
    for (int i = t; i < NB * NB; i += 512) {
        float p = h[i] * inv;
        ej += p * __logf(p + EPS);
    }
    #pragma unroll
    for (int o = 16; o; o >>= 1) ej += __shfl_down_sync(0xffffffffu, ej, o);
    if (lane == 0) warp_red[half][wih] = ej;
    __syncthreads();
    float sum_joint = 0.0f;
    if (wih == 0) {
        float v = (lane < 16) ? warp_red[half][lane] : 0.0f;
        #pragma unroll
        for (int o = 8; o; o >>= 1) v += __shfl_down_sync(0xffffffffu, v, o);
        sum_joint = v;  // valid in lane 0
    }
    __syncthreads();

    // ---- marginal sum p*log(p+eps) ----
    float em = 0.0f;
    if (t < NB) {
        em = px[half][t] * __logf(px[half][t] + EPS)
           + py[half][t] * __logf(py[half][t] + EPS);
    }
    #pragma unroll
    for (int o = 16; o; o >>= 1) em += __shfl_down_sync(0xffffffffu, em, o);
    if (lane == 0) warp_red[half][wih] = em;
    __syncthreads();
    if (wih == 0 && lane == 0) {
        float sum_marg = warp_red[half][0] + warp_red[half][1];  // warps 0,1 hold t<64
        // ent_xy = -sum_marg, ent_joint = -sum_joint -> ratio = sum_marg / sum_joint
        res[half] = sum_marg / sum_joint;
    }
    __syncthreads();
    if (tid == 0) out[0] = -0.5f * (res[0] + res[1]);

    // ---- re-zero scratch for the next graph replay ----
    for (int i = tid; i < NBATCH * NB * NB; i += 1024)
        ((float*)g_hist)[i] = 0.0f;
}

extern "C" void kernel_launch(void* const* d_in, const int* in_sizes, int n_in,
                              void* d_out, int out_size) {
    const float* x = (const float*)d_in[0];
    const float* y = (const float*)d_in[1];
    float* out = (float*)d_out;

    hist_kernel<<<dim3(BLOCKS_PER_BATCH, NBATCH), THREADS>>>(x, y);
    finalize_kernel<<<1, 1024>>>(out);
}

// round 7
// speedup vs baseline: 2.7780x; 1.0518x over previous
#include <cuda_runtime.h>
#include <cuda_fp16.h>

#define NBATCH 2
#define PPB (128*128*128)       // points per batch
#define NB 64                   // number of bins
#define NP 32                   // half2 pairs per row
#define BLOCKS_PER_BATCH 296
#define THREADS 256
#define FBLK 8                  // finalize blocks per batch

// Scratch (zero at module load; finalize re-zeroes everything for graph replay)
__device__ float g_hist[NBATCH][NB * NB];
__device__ float g_total[NBATCH];
__device__ float g_py[NBATCH][NB];
__device__ float g_ej[NBATCH];     // sum p*log(p+eps) over joint
__device__ float g_em[NBATCH];     // sum px*log(px+eps) over rows
__device__ unsigned int g_ticket;

__global__ __launch_bounds__(THREADS) void hist_kernel(const float* __restrict__ x,
                                                       const float* __restrict__ y) {
    __shared__ __half2 sh2[NB * NP];   // 64 rows x 32 half2 pairs
    __shared__ float red[8];
    const int n = blockIdx.y;
    for (int i = threadIdx.x; i < NB * NP; i += blockDim.x)
        ((unsigned int*)sh2)[i] = 0u;
    __syncthreads();

    // K2 = DELTA^2/(2 sigma^2); constants folded, GN dropped (cancels under norm).
    const float K2 = (float)( (1.0/63.0)*(1.0/63.0)
                     / (2.0 * (0.015625/2.3548200450309493) * (0.015625/2.3548200450309493)) );

    const float4* x4 = (const float4*)(x + (size_t)n * PPB);
    const float4* y4 = (const float4*)(y + (size_t)n * PPB);
    const int nvec = PPB / 4;
    const int stride = gridDim.x * blockDim.x;

    for (int v = blockIdx.x * blockDim.x + threadIdx.x; v < nvec; v += stride) {
        float4 xv = x4[v];
        float4 yv = y4[v];
        float xs[4] = {xv.x, xv.y, xv.z, xv.w};
        float ys[4] = {yv.x, yv.y, yv.z, yv.w};
        #pragma unroll
        for (int e = 0; e < 4; e++) {
            float fx = xs[e] * 63.0f;
            int ix = __float2int_rn(fx);
            float ux = fx - (float)ix;
            float wxm = __expf(-K2 * (ux + 1.0f) * (ux + 1.0f));
            float wx0 = __expf(-K2 * ux * ux);
            float wxp = __expf(-K2 * (ux - 1.0f) * (ux - 1.0f));
            float fy = ys[e] * 63.0f;
            int iy = __float2int_rn(fy);
            float uy = fy - (float)iy;
            float wym = __expf(-K2 * (uy + 1.0f) * (uy + 1.0f));
            float wy0 = __expf(-K2 * uy * uy);
            float wyp = __expf(-K2 * (uy - 1.0f) * (uy - 1.0f));

            // edges: zero weight + clamp index
            int rm = ix - 1, r0 = ix, rp = ix + 1;
            if (rm < 0)      { wxm = 0.0f; rm = 0; }
            if (rp > NB - 1) { wxp = 0.0f; rp = NB - 1; }
            if (iy < 1)       wym = 0.0f;
            if (iy > NB - 2)  wyp = 0.0f;

            // pack col taps {iy-1,iy,iy+1} into two aligned half2 pairs
            int par = iy & 1;
            int p0 = (iy - 1) >> 1;
            int p1 = p0 + 1;
            if (p0 < 0)      p0 = 0;
            if (p1 > NP - 1) p1 = NP - 1;
            float a0 = par ? wym : 0.0f;
            float b0 = par ? wy0 : wym;
            float a1 = par ? wyp : wy0;
            float b1 = par ? 0.0f : wyp;

            __half2 hy0 = __floats2half2_rn(a0, b0);
            __half2 hy1 = __floats2half2_rn(a1, b1);
            __half2 hxm = __float2half2_rn(wxm);
            __half2 hx0 = __float2half2_rn(wx0);
            __half2 hxp = __float2half2_rn(wxp);

            rm *= NP; r0 *= NP; rp *= NP;
            atomicAdd(&sh2[rm + p0], __hmul2(hxm, hy0));
            atomicAdd(&sh2[rm + p1], __hmul2(hxm, hy1));
            atomicAdd(&sh2[r0 + p0], __hmul2(hx0, hy0));
            atomicAdd(&sh2[r0 + p1], __hmul2(hx0, hy1));
            atomicAdd(&sh2[rp + p0], __hmul2(hxp, hy0));
            atomicAdd(&sh2[rp + p1], __hmul2(hxp, hy1));
        }
    }

    __syncthreads();
    // flush to global + block partial total mass
    float s = 0.0f;
    for (int i = threadIdx.x; i < NB * NP; i += blockDim.x) {
        float2 f = __half22float2(sh2[i]);
        s += f.x + f.y;
        atomicAdd(&g_hist[n][2 * i],     f.x);
        atomicAdd(&g_hist[n][2 * i + 1], f.y);
    }
    #pragma unroll
    for (int o = 16; o; o >>= 1) s += __shfl_down_sync(0xffffffffu, s, o);
    if ((threadIdx.x & 31) == 0) red[threadIdx.x >> 5] = s;
    __syncthreads();
    if (threadIdx.x == 0) {
        float t = 0.0f;
        #pragma unroll
        for (int w = 0; w < THREADS / 32; w++) t += red[w];
        atomicAdd(&g_total[n], t);
    }
}

// grid = NBATCH*FBLK blocks, 256 threads. Block (n,b) owns rows [8b, 8b+8).
__global__ __launch_bounds__(256) void finalize_kernel(float* __restrict__ out) {
    __shared__ float red[8];
    __shared__ float pycol[NB];
    __shared__ unsigned int s_last;
    const float EPS = 1e-5f;
    const int n = blockIdx.x >> 3;
    const int b = blockIdx.x & 7;
    float* h = g_hist[n] + b * 8 * NB;      // 512 cells
    const float inv = 1.0f / (g_total[n] + EPS);
    const int t = threadIdx.x;
    const int lane = t & 31;
    const int w = t >> 5;                   // warp = local row

    // ---- load the 2 cells this thread owns (row w, cols lane & lane+32) ----
    float c0 = h[w * NB + lane];
    float c1 = h[w * NB + lane + 32];

    // ---- joint entropy partial ----
    float p0 = c0 * inv, p1 = c1 * inv;
    float ej = p0 * __logf(p0 + EPS) + p1 * __logf(p1 + EPS);
    #pragma unroll
    for (int o = 16; o; o >>= 1) ej += __shfl_down_sync(0xffffffffu, ej, o);

    // ---- row sum (px) : warp w owns row w ----
    float rs = c0 + c1;
    #pragma unroll
    for (int o = 16; o; o >>= 1) rs += __shfl_down_sync(0xffffffffu, rs, o);
    float em = 0.0f;
    if (lane == 0) {
        float px = rs * inv;
        em = px * __logf(px + EPS);
        red[w] = ej;
    }
    __syncthreads();
    if (t == 0) {
        float e = 0.0f;
        #pragma unroll
        for (int i = 0; i < 8; i++) e += red[i];
        atomicAdd(&g_ej[n], e);
    }
    if (lane == 0) atomicAdd(&g_em[n], em);

    // ---- column partials (py, normalized): sum 8 rows per column ----
    if (t < NB) {
        float cs = 0.0f;
        #pragma unroll
        for (int r = 0; r < 8; r++) cs += h[r * NB + t];
        atomicAdd(&g_py[n][t], cs * inv);
    }

    // BARRIER: the py loop above (warps 0-1) reads ALL rows of this block's
    // slice; the zeroing below is done by all warps. Without this barrier,
    // warps 2-7 zero cells before warps 0-1 have read them (R6 bug, 24% err).
    __syncthreads();

    // ---- zero our hist slice for next replay ----
    h[w * NB + lane] = 0.0f;
    h[w * NB + lane + 32] = 0.0f;

    __threadfence();
    __syncthreads();
    if (t == 0) s_last = atomicInc(&g_ticket, NBATCH * FBLK - 1);  // wraps to 0
    __syncthreads();

    if (s_last == NBATCH * FBLK - 1) {
        __threadfence();
        // py entropies: t<64 -> batch0 col t ; t in [64,128) -> batch1
        float e = 0.0f;
        if (t < NBATCH * NB) {
            int nn = t >> 6, c = t & 63;
            float v = g_py[nn][c];
            e = v * __logf(v + EPS);
            g_py[nn][c] = 0.0f;             // reset for next replay
        }
        // reduce per batch: warps 0,1 = batch0 ; warps 2,3 = batch1
        #pragma unroll
        for (int o = 16; o; o >>= 1) e += __shfl_down_sync(0xffffffffu, e, o);
        if (lane == 0 && w < 4) pycol[w] = e;
        __syncthreads();
        if (t == 0) {
            float epy0 = pycol[0] + pycol[1];
            float epy1 = pycol[2] + pycol[3];
            float r0 = (g_em[0] + epy0) / g_ej[0];
            float r1 = (g_em[1] + epy1) / g_ej[1];
            out[0] = -0.5f * (r0 + r1);
            // reset scalars for next replay
            g_em[0] = g_em[1] = 0.0f;
            g_ej[0] = g_ej[1] = 0.0f;
            g_total[0] = g_total[1] = 0.0f;
        }
    }
}

extern "C" void kernel_launch(void* const* d_in, const int* in_sizes, int n_in,
                              void* d_out, int out_size) {
    const float* x = (const float*)d_in[0];
    const float* y = (const float*)d_in[1];
    float* out = (float*)d_out;

    hist_kernel<<<dim3(BLOCKS_PER_BATCH, NBATCH), THREADS>>>(x, y);
    finalize_kernel<<<NBATCH * FBLK, 256>>>(out);
}

// round 8
// speedup vs baseline: 3.0000x; 1.0799x over previous
#include <cuda_runtime.h>
#include <cuda_fp16.h>

#define NBATCH 2
#define PPB (128*128*128)       // points per batch
#define NB 64                   // number of bins
#define BLOCKS_PER_BATCH 296
#define THREADS 256
#define FBLK 8                  // finalize blocks per batch

// Plane layout: 2 parity planes, each 66 stored rows x 34 half2 pairs.
// Stored row = logical row + 1 (rows 0 and 65 are guards).
// Pair q in plane p: lo accumulates col (2q-2+p) [wym&wyp taps], hi col (2q-1+p) [wy0].
// Guards: pair-0 lo (col<0), pair 33 (col>=64) -- discarded at flush.
#define PROWS 66
#define PPAIR 34
#define PS (PROWS * PPAIR)      // 2244 half2 per plane

// Scratch (zero at module load; finalize re-zeroes everything for graph replay)
__device__ float g_hist[NBATCH][NB * NB];
__device__ float g_total[NBATCH];
__device__ float g_py[NBATCH][NB];
__device__ float g_ej[NBATCH];     // sum p*log(p+eps) over joint
__device__ float g_em[NBATCH];     // sum px*log(px+eps) over rows
__device__ unsigned int g_ticket;

__global__ __launch_bounds__(THREADS) void hist_kernel(const float* __restrict__ x,
                                                       const float* __restrict__ y) {
    __shared__ __half2 sh2[2 * PS];
    __shared__ float red[8];
    const int n = blockIdx.y;
    for (int i = threadIdx.x; i < 2 * PS; i += blockDim.x)
        ((unsigned int*)sh2)[i] = 0u;
    __syncthreads();

    // K2 = DELTA^2/(2 sigma^2); constants folded, GN dropped (cancels under norm).
    const float K2 = (float)( (1.0/63.0)*(1.0/63.0)
                     / (2.0 * (0.015625/2.3548200450309493) * (0.015625/2.3548200450309493)) );

    const float4* x4 = (const float4*)(x + (size_t)n * PPB);
    const float4* y4 = (const float4*)(y + (size_t)n * PPB);
    const int nvec = PPB / 4;
    const int stride = gridDim.x * blockDim.x;

    for (int v = blockIdx.x * blockDim.x + threadIdx.x; v < nvec; v += stride) {
        float4 xv = x4[v];
        float4 yv = y4[v];
        float xs[4] = {xv.x, xv.y, xv.z, xv.w};
        float ys[4] = {yv.x, yv.y, yv.z, yv.w};
        #pragma unroll
        for (int e = 0; e < 4; e++) {
            // ---- x weights: args A = -K2*u^2, A -/+ K2*(2u +/- 1)
            float fx = xs[e] * 63.0f;
            int ix = __float2int_rn(fx);
            float ux = fx - (float)ix;
            float Ax = -K2 * ux * ux;
            float Bx = (2.0f * K2) * ux;
            float wx0 = __expf(Ax);
            float wxm = __expf(Ax - Bx - K2);
            float wxp = __expf(Ax + Bx - K2);
            // ---- y weights
            float fy = ys[e] * 63.0f;
            int iy = __float2int_rn(fy);
            float uy = fy - (float)iy;
            float Ay = -K2 * uy * uy;
            float By = (2.0f * K2) * uy;
            float wy0 = __expf(Ay);
            float wym = __expf(Ay - By - K2);
            float wyp = __expf(Ay + By - K2);

            // ---- plane address: no edge handling needed (guard cells absorb)
            int par = iy & 1;
            int q0 = ((iy - 1) >> 1) + 1;              // 0..32
            int base = par * PS + ix * PPAIR + q0;     // stored row = ix (logical ix-1)

            __half2 hy0 = __floats2half2_rn(wym, wy0);
            __half2 hy1 = __floats2half2_rn(wyp, 0.0f);
            __half2 hxm = __float2half2_rn(wxm);
            __half2 hx0 = __float2half2_rn(wx0);
            __half2 hxp = __float2half2_rn(wxp);

            atomicAdd(&sh2[base],              __hmul2(hxm, hy0));
            atomicAdd(&sh2[base + 1],          __hmul2(hxm, hy1));
            atomicAdd(&sh2[base + PPAIR],      __hmul2(hx0, hy0));
            atomicAdd(&sh2[base + PPAIR + 1],  __hmul2(hx0, hy1));
            atomicAdd(&sh2[base + 2*PPAIR],    __hmul2(hxp, hy0));
            atomicAdd(&sh2[base + 2*PPAIR + 1],__hmul2(hxp, hy1));
        }
    }

    __syncthreads();
    // ---- de-plane flush to global + block partial total mass (interior only)
    float s = 0.0f;
    for (int i = threadIdx.x; i < NB * NB; i += blockDim.x) {
        int r = i >> 6, c = i & 63;
        int sr = (r + 1) * PPAIR;                      // stored row base
        float val;
        if (c & 1) {
            int q = (c + 1) >> 1;
            val = __low2float(sh2[sr + q])             // plane0 lo
                + __high2float(sh2[PS + sr + q]);      // plane1 hi
        } else {
            val = __low2float(sh2[PS + sr + (c >> 1) + 1])  // plane1 lo
                + __high2float(sh2[sr + (c >> 1)]);         // plane0 hi
        }
        s += val;
        atomicAdd(&g_hist[n][i], val);
    }
    #pragma unroll
    for (int o = 16; o; o >>= 1) s += __shfl_down_sync(0xffffffffu, s, o);
    if ((threadIdx.x & 31) == 0) red[threadIdx.x >> 5] = s;
    __syncthreads();
    if (threadIdx.x == 0) {
        float t = 0.0f;
        #pragma unroll
        for (int w = 0; w < THREADS / 32; w++) t += red[w];
        atomicAdd(&g_total[n], t);
    }
}

// grid = NBATCH*FBLK blocks, 256 threads. Block (n,b) owns rows [8b, 8b+8).
__global__ __launch_bounds__(256) void finalize_kernel(float* __restrict__ out) {
    __shared__ float red[8];
    __shared__ float pycol[NB];
    __shared__ unsigned int s_last;
    const float EPS = 1e-5f;
    const int n = blockIdx.x >> 3;
    const int b = blockIdx.x & 7;
    float* h = g_hist[n] + b * 8 * NB;      // 512 cells
    const float inv = 1.0f / (g_total[n] + EPS);
    const int t = threadIdx.x;
    const int lane = t & 31;
    const int w = t >> 5;                   // warp = local row

    float c0 = h[w * NB + lane];
    float c1 = h[w * NB + lane + 32];

    // joint entropy partial
    float p0 = c0 * inv, p1 = c1 * inv;
    float ej = p0 * __logf(p0 + EPS) + p1 * __logf(p1 + EPS);
    #pragma unroll
    for (int o = 16; o; o >>= 1) ej += __shfl_down_sync(0xffffffffu, ej, o);

    // row sum (px): warp w owns row w
    float rs = c0 + c1;
    #pragma unroll
    for (int o = 16; o; o >>= 1) rs += __shfl_down_sync(0xffffffffu, rs, o);
    float em = 0.0f;
    if (lane == 0) {
        float px = rs * inv;
        em = px * __logf(px + EPS);
        red[w] = ej;
    }
    __syncthreads();
    if (t == 0) {
        float e = 0.0f;
        #pragma unroll
        for (int i = 0; i < 8; i++) e += red[i];
        atomicAdd(&g_ej[n], e);
    }
    if (lane == 0) atomicAdd(&g_em[n], em);

    // column partials (py, normalized)
    if (t < NB) {
        float cs = 0.0f;
        #pragma unroll
        for (int r = 0; r < 8; r++) cs += h[r * NB + t];
        atomicAdd(&g_py[n][t], cs * inv);
    }

    // BARRIER: py loop (warps 0-1) reads ALL rows of this slice; zeroing below
    // is done by all warps (R6 bug: without this, data was zeroed before read).
    __syncthreads();

    h[w * NB + lane] = 0.0f;
    h[w * NB + lane + 32] = 0.0f;

    __threadfence();
    __syncthreads();
    if (t == 0) s_last = atomicInc(&g_ticket, NBATCH * FBLK - 1);  // wraps to 0
    __syncthreads();

    if (s_last == NBATCH * FBLK - 1) {
        __threadfence();
        float e = 0.0f;
        if (t < NBATCH * NB) {
            int nn = t >> 6, c = t & 63;
            float v = g_py[nn][c];
            e = v * __logf(v + EPS);
            g_py[nn][c] = 0.0f;
        }
        #pragma unroll
        for (int o = 16; o; o >>= 1) e += __shfl_down_sync(0xffffffffu, e, o);
        if (lane == 0 && w < 4) pycol[w] = e;
        __syncthreads();
        if (t == 0) {
            float epy0 = pycol[0] + pycol[1];
            float epy1 = pycol[2] + pycol[3];
            float r0 = (g_em[0] + epy0) / g_ej[0];
            float r1 = (g_em[1] + epy1) / g_ej[1];
            out[0] = -0.5f * (r0 + r1);
            g_em[0] = g_em[1] = 0.0f;
            g_ej[0] = g_ej[1] = 0.0f;
            g_total[0] = g_total[1] = 0.0f;
        }
    }
}

extern "C" void kernel_launch(void* const* d_in, const int* in_sizes, int n_in,
                              void* d_out, int out_size) {
    const float* x = (const float*)d_in[0];
    const float* y = (const float*)d_in[1];
    float* out = (float*)d_out;

    hist_kernel<<<dim3(BLOCKS_PER_BATCH, NBATCH), THREADS>>>(x, y);
    finalize_kernel<<<NBATCH * FBLK, 256>>>(out);
}